// round 1
// baseline (speedup 1.0000x reference)
#include <cuda_runtime.h>
#include <math.h>

#define DIM 4096
#define HID 8192
#define ALPHA 0.1f
#define LOG_ALPHA -2.3025850929940457f

// Scratch (device globals are the sanctioned scratch mechanism).
static __device__ float g_c[(size_t)DIM * HID];   // c[i*HID + b] = u*x[b,i] + a  (transposed)
static __device__ float g_A[DIM];                 // f_i(0)
static __device__ float g_B[DIM];                 // f_i'(0)
static __device__ float g_V1[DIM];                // V after linearized scan
static __device__ float g_V2[DIM];                // V after Jacobi pass 1
static __device__ float g_V3[DIM];                // V after Jacobi pass 2
static __device__ float g_W[DIM];                 // W_i

// ---------------------------------------------------------------------------
// Block-wide sum reduction, blockDim.x == 256 (8 warps).
// Result valid on warp 0 (all lanes). sm must hold >= 8 floats.
__device__ __forceinline__ float block_reduce_256(float val, float* sm) {
#pragma unroll
    for (int o = 16; o > 0; o >>= 1)
        val += __shfl_xor_sync(0xffffffffu, val, o);
    int warp = threadIdx.x >> 5;
    if ((threadIdx.x & 31) == 0) sm[warp] = val;
    __syncthreads();
    if (warp == 0) {
        val = (threadIdx.x < 8) ? sm[threadIdx.x] : 0.f;
#pragma unroll
        for (int o = 4; o > 0; o >>= 1)
            val += __shfl_xor_sync(0xffffffffu, val, o);
    }
    return val;
}

// ---------------------------------------------------------------------------
// Kernel A: transpose + affine.  x:[HID, DIM] row-major -> g_c[i][b] = u*x[b,i] + a
__global__ __launch_bounds__(256) void k_transpose(
    const float* __restrict__ x,
    const float* __restrict__ u_p,
    const float* __restrict__ a_p)
{
    __shared__ float tile[32][33];
    const float u = u_p[0];
    const float a = a_p[0];
    const int i0 = blockIdx.x * 32;   // i tile base
    const int b0 = blockIdx.y * 32;   // b tile base
    const int tx = threadIdx.x;       // 0..31
    const int ty = threadIdx.y;       // 0..7

#pragma unroll
    for (int r = 0; r < 32; r += 8)
        tile[ty + r][tx] = x[(size_t)(b0 + ty + r) * DIM + (i0 + tx)];
    __syncthreads();
#pragma unroll
    for (int r = 0; r < 32; r += 8)
        g_c[(size_t)(i0 + ty + r) * HID + (b0 + tx)] = fmaf(u, tile[tx][ty + r], a);
}

// ---------------------------------------------------------------------------
// Kernel P1: per-column linearization.  A_i = sum v_b*relu(c), B_i = sum_{c>0} v_b
__global__ __launch_bounds__(256) void k_pass1(const float* __restrict__ v)
{
    const int i = blockIdx.x;
    const float* __restrict__ c = &g_c[(size_t)i * HID];
    float accA = 0.f, accB = 0.f;
#pragma unroll 4
    for (int b = threadIdx.x; b < HID; b += 256) {
        float cv = c[b];
        float vv = v[b];
        accA = fmaf(vv, fmaxf(cv, 0.f), accA);
        if (cv > 0.f) accB += vv;
    }
    __shared__ float smA[8];
    __shared__ float smB[8];
    float A = block_reduce_256(accA, smA);
    float B = block_reduce_256(accB, smB);
    if (threadIdx.x == 0) { g_A[i] = A; g_B[i] = B; }
}

// ---------------------------------------------------------------------------
// Kernel S: sequential affine scan V_{i} = A_{i-1} + B_{i-1} * V_{i-1}.
// Staged through shared memory; single-thread dependent chain is ~4 cyc/step.
__global__ __launch_bounds__(1024) void k_scan()
{
    __shared__ float sA[DIM];
    __shared__ float sB[DIM];
    __shared__ float sV[DIM];
    for (int i = threadIdx.x; i < DIM; i += 1024) {
        sA[i] = g_A[i];
        sB[i] = g_B[i];
    }
    __syncthreads();
    if (threadIdx.x == 0) {
        float V = 0.f;
        sV[0] = 0.f;
#pragma unroll 8
        for (int i = 1; i < DIM; ++i) {
            V = fmaf(sB[i - 1], V, sA[i - 1]);
            sV[i] = V;
        }
    }
    __syncthreads();
    for (int i = threadIdx.x; i < DIM; i += 1024)
        g_V1[i] = sV[i];
}

// ---------------------------------------------------------------------------
// Kernel J: Jacobi refinement.  Vout[i+1] = sum_b v_b * relu(c[i][b] + Vin[i]).
// pass==0: g_V1 -> g_V2 ; pass==1: g_V2 -> g_V3
__global__ __launch_bounds__(256) void k_jacobi(const float* __restrict__ v, int pass)
{
    const int i = blockIdx.x;                       // 0..DIM-2
    const float* __restrict__ Vin = pass ? g_V2 : g_V1;
    float* __restrict__ Vout      = pass ? g_V3 : g_V2;
    const float V = Vin[i];
    const float* __restrict__ c = &g_c[(size_t)i * HID];
    float acc = 0.f;
#pragma unroll 4
    for (int b = threadIdx.x; b < HID; b += 256)
        acc = fmaf(v[b], fmaxf(c[b] + V, 0.f), acc);
    __shared__ float sm[8];
    float s = block_reduce_256(acc, sm);
    if (threadIdx.x == 0) {
        Vout[i + 1] = s;
        if (i == 0) Vout[0] = 0.f;
    }
}

// ---------------------------------------------------------------------------
// Kernel W: W_j = sum_b w_b * relu(c[j-1][b] + V_{j-1}),  W_0 = 0.
__global__ __launch_bounds__(256) void k_wpass(const float* __restrict__ w)
{
    const int j = blockIdx.x;                       // 0..DIM-1
    if (j == 0) {
        if (threadIdx.x == 0) g_W[0] = 0.f;
        return;
    }
    const float V = g_V3[j - 1];
    const float* __restrict__ c = &g_c[(size_t)(j - 1) * HID];
    float acc = 0.f;
#pragma unroll 4
    for (int b = threadIdx.x; b < HID; b += 256)
        acc = fmaf(w[b], fmaxf(c[b] + V, 0.f), acc);
    __shared__ float sm[8];
    float s = block_reduce_256(acc, sm);
    if (threadIdx.x == 0) g_W[j] = s;
}

// ---------------------------------------------------------------------------
// Kernel Z: z[b,i] = leaky(y*x[b,i] + W_i + b0); logdet[b] = DIM*log|y| + cnt*log(alpha)
__global__ __launch_bounds__(256) void k_z(
    const float* __restrict__ x,
    const float* __restrict__ y_p,
    const float* __restrict__ b_p,
    float* __restrict__ out)
{
    const int row = blockIdx.x;                     // 0..HID-1
    const float y0 = y_p[0];
    const float b0 = b_p[0];
    const float* __restrict__ xr = &x[(size_t)row * DIM];
    float* __restrict__ zr = &out[(size_t)row * DIM];
    float cnt = 0.f;                                // # negative lins (exact in fp32)
#pragma unroll
    for (int j = 0; j < DIM / 256; ++j) {
        const int i = j * 256 + threadIdx.x;
        float lin = fmaf(y0, xr[i], g_W[i] + b0);
        bool pos = (lin >= 0.f);
        zr[i] = pos ? lin : (ALPHA * lin);
        if (!pos) cnt += 1.f;
    }
    __shared__ float sm[8];
    float c = block_reduce_256(cnt, sm);
    if (threadIdx.x == 0)
        out[(size_t)HID * DIM + row] =
            c * LOG_ALPHA + (float)DIM * logf(fabsf(y0));
}

// ---------------------------------------------------------------------------
extern "C" void kernel_launch(void* const* d_in, const int* in_sizes, int n_in,
                              void* d_out, int out_size)
{
    (void)in_sizes; (void)n_in; (void)out_size;
    const float* x = (const float*)d_in[0];   // [HID, DIM]
    const float* y = (const float*)d_in[1];   // [1]
    const float* w = (const float*)d_in[2];   // [HID]
    const float* b = (const float*)d_in[3];   // [1]
    const float* u = (const float*)d_in[4];   // [1]
    const float* v = (const float*)d_in[5];   // [HID]
    const float* a = (const float*)d_in[6];   // [1]
    float* out = (float*)d_out;               // [HID*DIM] z  +  [HID] logdet

    k_transpose<<<dim3(DIM / 32, HID / 32), dim3(32, 8)>>>(x, u, a);
    k_pass1<<<DIM, 256>>>(v);
    k_scan<<<1, 1024>>>();
    k_jacobi<<<DIM - 1, 256>>>(v, 0);
    k_jacobi<<<DIM - 1, 256>>>(v, 1);
    k_wpass<<<DIM, 256>>>(w);
    k_z<<<HID, 256>>>(x, y, b, out);
}

// round 2
// speedup vs baseline: 2.3193x; 2.3193x over previous
#include <cuda_runtime.h>
#include <math.h>

#define DIM 4096
#define HID 8192
#define ALPHA 0.1f
#define LOG_ALPHA -2.3025850929940457f

#define ICHUNK 1024            // columns per block (256 thr x 4 via float4)
#define BROWS  32              // rows per block
#define NSLAB  (HID / BROWS)   // 256 partial slabs

// Scratch (device globals are the sanctioned scratch mechanism). ~8MB total.
static __device__ __align__(16) float g_partA[(size_t)NSLAB * DIM];
static __device__ __align__(16) float g_partB[(size_t)NSLAB * DIM];
static __device__ __align__(16) float g_A[DIM];
static __device__ __align__(16) float g_B[DIM];
static __device__ __align__(16) float g_V1[DIM + 4];  // V1[i], i in [0,DIM]
static __device__ __align__(16) float g_W[DIM + 4];   // W[i],  i in [0,DIM]

// ---------------------------------------------------------------------------
// Block-wide sum reduction, blockDim.x == 256 (8 warps). Valid on warp 0.
__device__ __forceinline__ float block_reduce_256(float val, float* sm) {
#pragma unroll
    for (int o = 16; o > 0; o >>= 1)
        val += __shfl_xor_sync(0xffffffffu, val, o);
    int warp = threadIdx.x >> 5;
    if ((threadIdx.x & 31) == 0) sm[warp] = val;
    __syncthreads();
    if (warp == 0) {
        val = (threadIdx.x < 8) ? sm[threadIdx.x] : 0.f;
#pragma unroll
        for (int o = 4; o > 0; o >>= 1)
            val += __shfl_xor_sync(0xffffffffu, val, o);
    }
    return val;
}

// ---------------------------------------------------------------------------
// Stage-1 reduction over rows of x (row-major, no transpose):
//   partA[slab][i] = sum_{b in slab} v_b * relu(u*x[b,i] + a)
//   partB[slab][i] = sum_{b in slab, lin>0} v_b
__global__ __launch_bounds__(256) void k_red_ab(
    const float* __restrict__ x, const float* __restrict__ v,
    const float* __restrict__ u_p, const float* __restrict__ a_p)
{
    const float u = u_p[0];
    const float a = a_p[0];
    const int i0 = blockIdx.x * ICHUNK + threadIdx.x * 4;
    const int b0 = blockIdx.y * BROWS;
    float4 accA = make_float4(0.f, 0.f, 0.f, 0.f);
    float4 accB = make_float4(0.f, 0.f, 0.f, 0.f);
    const float* xp = x + (size_t)b0 * DIM + i0;
#pragma unroll 4
    for (int r = 0; r < BROWS; ++r) {
        const float vb = __ldg(&v[b0 + r]);
        const float4 xv = *(const float4*)(xp + (size_t)r * DIM);
        const float l0 = fmaf(u, xv.x, a);
        const float l1 = fmaf(u, xv.y, a);
        const float l2 = fmaf(u, xv.z, a);
        const float l3 = fmaf(u, xv.w, a);
        accA.x = fmaf(vb, fmaxf(l0, 0.f), accA.x);
        accA.y = fmaf(vb, fmaxf(l1, 0.f), accA.y);
        accA.z = fmaf(vb, fmaxf(l2, 0.f), accA.z);
        accA.w = fmaf(vb, fmaxf(l3, 0.f), accA.w);
        if (l0 > 0.f) accB.x += vb;
        if (l1 > 0.f) accB.y += vb;
        if (l2 > 0.f) accB.z += vb;
        if (l3 > 0.f) accB.w += vb;
    }
    const size_t po = (size_t)blockIdx.y * DIM + i0;
    *(float4*)&g_partA[po] = accA;
    *(float4*)&g_partB[po] = accB;
}

// ---------------------------------------------------------------------------
// Stage-2: deterministic fixed-order reduce of slabs -> g_A, g_B.
__global__ __launch_bounds__(256) void k_finred_ab()
{
    const int i = blockIdx.x * 256 + threadIdx.x;
    float sa0 = 0.f, sa1 = 0.f, sb0 = 0.f, sb1 = 0.f;
#pragma unroll 4
    for (int s = 0; s < NSLAB; s += 2) {
        sa0 += g_partA[(size_t)s * DIM + i];
        sa1 += g_partA[(size_t)(s + 1) * DIM + i];
        sb0 += g_partB[(size_t)s * DIM + i];
        sb1 += g_partB[(size_t)(s + 1) * DIM + i];
    }
    g_A[i] = sa0 + sa1;
    g_B[i] = sb0 + sb1;
}

// ---------------------------------------------------------------------------
// Parallel scan of the affine recurrence V[i+1] = A[i] + B[i]*V[i], V[0]=0.
// Affine maps compose associatively: (a2,b2)∘(a1,b1) = (a2+b2*a1, b2*b1).
// 1 block, 1024 threads; each thread locally composes 4 maps, then a
// Hillis-Steele scan over the 1024 thread-aggregates.
__global__ __launch_bounds__(1024) void k_scan()
{
    __shared__ float sa[1024];
    __shared__ float sb[1024];
    const int t = threadIdx.x;
    float la[4], lb[4];
    la[0] = g_A[4 * t];
    lb[0] = g_B[4 * t];
#pragma unroll
    for (int k = 1; k < 4; ++k) {
        const float A = g_A[4 * t + k];
        const float B = g_B[4 * t + k];
        la[k] = fmaf(B, la[k - 1], A);
        lb[k] = B * lb[k - 1];
    }
    sa[t] = la[3];
    sb[t] = lb[3];
    __syncthreads();
#pragma unroll
    for (int off = 1; off < 1024; off <<= 1) {
        float pa = 0.f, pb = 0.f;
        const bool has = (t >= off);
        if (has) { pa = sa[t - off]; pb = sb[t - off]; }
        __syncthreads();
        if (has) {
            sa[t] = fmaf(sb[t], pa, sa[t]);
            sb[t] = sb[t] * pb;
        }
        __syncthreads();
    }
    // exclusive prefix applied to V0 = 0  ->  prefix value pa
    const float pa = (t > 0) ? sa[t - 1] : 0.f;
#pragma unroll
    for (int k = 0; k < 4; ++k)
        g_V1[4 * t + k + 1] = fmaf(lb[k], pa, la[k]);
    if (t == 0) g_V1[0] = 0.f;
}

// ---------------------------------------------------------------------------
// Stage-1 reduction for W:
//   partA[slab][i] = sum_{b in slab} w_b * relu(u*x[b,i] + a + V1[i])
__global__ __launch_bounds__(256) void k_red_w(
    const float* __restrict__ x, const float* __restrict__ w,
    const float* __restrict__ u_p, const float* __restrict__ a_p)
{
    const float u = u_p[0];
    const float a = a_p[0];
    const int i0 = blockIdx.x * ICHUNK + threadIdx.x * 4;
    const int b0 = blockIdx.y * BROWS;
    const float4 vsh = *(const float4*)&g_V1[i0];
    const float s0 = a + vsh.x, s1 = a + vsh.y, s2 = a + vsh.z, s3 = a + vsh.w;
    float4 acc = make_float4(0.f, 0.f, 0.f, 0.f);
    const float* xp = x + (size_t)b0 * DIM + i0;
#pragma unroll 4
    for (int r = 0; r < BROWS; ++r) {
        const float wb = __ldg(&w[b0 + r]);
        const float4 xv = *(const float4*)(xp + (size_t)r * DIM);
        acc.x = fmaf(wb, fmaxf(fmaf(u, xv.x, s0), 0.f), acc.x);
        acc.y = fmaf(wb, fmaxf(fmaf(u, xv.y, s1), 0.f), acc.y);
        acc.z = fmaf(wb, fmaxf(fmaf(u, xv.z, s2), 0.f), acc.z);
        acc.w = fmaf(wb, fmaxf(fmaf(u, xv.w, s3), 0.f), acc.w);
    }
    *(float4*)&g_partA[(size_t)blockIdx.y * DIM + i0] = acc;
}

// ---------------------------------------------------------------------------
// Stage-2 for W: g_W[i+1] = sum_slabs partA[.][i];  g_W[0] = 0.
__global__ __launch_bounds__(256) void k_finred_w()
{
    const int i = blockIdx.x * 256 + threadIdx.x;
    float s0 = 0.f, s1 = 0.f;
#pragma unroll 4
    for (int s = 0; s < NSLAB; s += 2) {
        s0 += g_partA[(size_t)s * DIM + i];
        s1 += g_partA[(size_t)(s + 1) * DIM + i];
    }
    g_W[i + 1] = s0 + s1;
    if (i == 0) g_W[0] = 0.f;
}

// ---------------------------------------------------------------------------
// z[b,i] = leaky(y*x[b,i] + W_i + b0); logdet[b] = DIM*log|y| + cnt_neg*log(alpha)
__global__ __launch_bounds__(256) void k_z(
    const float* __restrict__ x,
    const float* __restrict__ y_p,
    const float* __restrict__ b_p,
    float* __restrict__ out)
{
    const int row = blockIdx.x;
    const float y0 = y_p[0];
    const float bb = b_p[0];
    const float4* __restrict__ xr = (const float4*)(x + (size_t)row * DIM);
    float4* __restrict__ zr = (float4*)(out + (size_t)row * DIM);
    float cnt = 0.f;
#pragma unroll
    for (int j = 0; j < DIM / 4 / 256; ++j) {   // 4 iterations
        const int c = j * 256 + threadIdx.x;
        const float4 xv = xr[c];
        const float4 wv = *(const float4*)&g_W[4 * c];
        float4 z;
        const float l0 = fmaf(y0, xv.x, wv.x + bb);
        const float l1 = fmaf(y0, xv.y, wv.y + bb);
        const float l2 = fmaf(y0, xv.z, wv.z + bb);
        const float l3 = fmaf(y0, xv.w, wv.w + bb);
        z.x = (l0 >= 0.f) ? l0 : ALPHA * l0; if (l0 < 0.f) cnt += 1.f;
        z.y = (l1 >= 0.f) ? l1 : ALPHA * l1; if (l1 < 0.f) cnt += 1.f;
        z.z = (l2 >= 0.f) ? l2 : ALPHA * l2; if (l2 < 0.f) cnt += 1.f;
        z.w = (l3 >= 0.f) ? l3 : ALPHA * l3; if (l3 < 0.f) cnt += 1.f;
        zr[c] = z;
    }
    __shared__ float sm[8];
    const float c = block_reduce_256(cnt, sm);
    if (threadIdx.x == 0)
        out[(size_t)HID * DIM + row] = c * LOG_ALPHA + (float)DIM * logf(fabsf(y0));
}

// ---------------------------------------------------------------------------
extern "C" void kernel_launch(void* const* d_in, const int* in_sizes, int n_in,
                              void* d_out, int out_size)
{
    (void)in_sizes; (void)n_in; (void)out_size;
    const float* x = (const float*)d_in[0];   // [HID, DIM]
    const float* y = (const float*)d_in[1];   // [1]
    const float* w = (const float*)d_in[2];   // [HID]
    const float* b = (const float*)d_in[3];   // [1]
    const float* u = (const float*)d_in[4];   // [1]
    const float* v = (const float*)d_in[5];   // [HID]
    const float* a = (const float*)d_in[6];   // [1]
    float* out = (float*)d_out;               // [HID*DIM] z + [HID] logdet

    k_red_ab<<<dim3(DIM / ICHUNK, NSLAB), 256>>>(x, v, u, a);
    k_finred_ab<<<DIM / 256, 256>>>();
    k_scan<<<1, 1024>>>();
    k_red_w<<<dim3(DIM / ICHUNK, NSLAB), 256>>>(x, w, u, a);
    k_finred_w<<<DIM / 256, 256>>>();
    k_z<<<HID, 256>>>(x, y, b, out);
}

// round 3
// speedup vs baseline: 3.2918x; 1.4193x over previous
#include <cuda_runtime.h>
#include <math.h>

#define DIM 4096
#define HID 8192
#define ALPHA 0.1f
#define LOG_ALPHA -2.3025850929940457f

#define ICHUNK 1024            // columns per block in stage-1 (256 thr x 4)
#define BROWS  64              // rows per block in stage-1
#define NSLAB  (HID / BROWS)   // 128 partial slabs

// Scratch (device globals). 4 partial arrays, 2 MB each = 8 MB.
static __device__ __align__(16) float g_pAv[(size_t)NSLAB * DIM];
static __device__ __align__(16) float g_pBv[(size_t)NSLAB * DIM];
static __device__ __align__(16) float g_pAw[(size_t)NSLAB * DIM];
static __device__ __align__(16) float g_pBw[(size_t)NSLAB * DIM];
static __device__ __align__(16) float g_Av[DIM];
static __device__ __align__(16) float g_Bv[DIM];
static __device__ __align__(16) float g_Aw[DIM];
static __device__ __align__(16) float g_Bw[DIM];
static __device__ __align__(16) float g_W[DIM + 4];   // W[i], i in [0,DIM]

// ---------------------------------------------------------------------------
// Block-wide sum reduction, blockDim.x == 256 (8 warps). Valid on warp 0.
__device__ __forceinline__ float block_reduce_256(float val, float* sm) {
#pragma unroll
    for (int o = 16; o > 0; o >>= 1)
        val += __shfl_xor_sync(0xffffffffu, val, o);
    int warp = threadIdx.x >> 5;
    if ((threadIdx.x & 31) == 0) sm[warp] = val;
    __syncthreads();
    if (warp == 0) {
        val = (threadIdx.x < 8) ? sm[threadIdx.x] : 0.f;
#pragma unroll
        for (int o = 4; o > 0; o >>= 1)
            val += __shfl_xor_sync(0xffffffffu, val, o);
    }
    return val;
}

// ---------------------------------------------------------------------------
// Stage-1: ONE pass over x computing all four column statistics per slab:
//   pAv[s][i] = sum_{b in s} v_b * relu(c)     pBv[s][i] = sum_{b in s, c>0} v_b
//   pAw[s][i] = sum_{b in s} w_b * relu(c)     pBw[s][i] = sum_{b in s, c>0} w_b
// where c = u*x[b,i] + a.
__global__ __launch_bounds__(256) void k_red4(
    const float* __restrict__ x, const float* __restrict__ v,
    const float* __restrict__ w,
    const float* __restrict__ u_p, const float* __restrict__ a_p)
{
    const float u = u_p[0];
    const float a = a_p[0];
    const int i0 = blockIdx.x * ICHUNK + threadIdx.x * 4;
    const int b0 = blockIdx.y * BROWS;
    float4 Av = make_float4(0.f, 0.f, 0.f, 0.f);
    float4 Bv = make_float4(0.f, 0.f, 0.f, 0.f);
    float4 Aw = make_float4(0.f, 0.f, 0.f, 0.f);
    float4 Bw = make_float4(0.f, 0.f, 0.f, 0.f);
    const float* xp = x + (size_t)b0 * DIM + i0;
#pragma unroll 4
    for (int r = 0; r < BROWS; ++r) {
        const float vb = __ldg(&v[b0 + r]);
        const float wb = __ldg(&w[b0 + r]);
        const float4 xv = *(const float4*)(xp + (size_t)r * DIM);
        const float l0 = fmaf(u, xv.x, a);
        const float l1 = fmaf(u, xv.y, a);
        const float l2 = fmaf(u, xv.z, a);
        const float l3 = fmaf(u, xv.w, a);
        const float r0 = fmaxf(l0, 0.f), r1 = fmaxf(l1, 0.f);
        const float r2 = fmaxf(l2, 0.f), r3 = fmaxf(l3, 0.f);
        Av.x = fmaf(vb, r0, Av.x);  Aw.x = fmaf(wb, r0, Aw.x);
        Av.y = fmaf(vb, r1, Av.y);  Aw.y = fmaf(wb, r1, Aw.y);
        Av.z = fmaf(vb, r2, Av.z);  Aw.z = fmaf(wb, r2, Aw.z);
        Av.w = fmaf(vb, r3, Av.w);  Aw.w = fmaf(wb, r3, Aw.w);
        if (l0 > 0.f) { Bv.x += vb; Bw.x += wb; }
        if (l1 > 0.f) { Bv.y += vb; Bw.y += wb; }
        if (l2 > 0.f) { Bv.z += vb; Bw.z += wb; }
        if (l3 > 0.f) { Bv.w += vb; Bw.w += wb; }
    }
    const size_t po = (size_t)blockIdx.y * DIM + i0;
    *(float4*)&g_pAv[po] = Av;
    *(float4*)&g_pBv[po] = Bv;
    *(float4*)&g_pAw[po] = Aw;
    *(float4*)&g_pBw[po] = Bw;
}

// ---------------------------------------------------------------------------
// Stage-2: reduce NSLAB slabs -> A/B vectors. 64 blocks x 256 threads.
// Block covers 64 columns; 4 thread-groups of 64 each sum NSLAB/4 slabs,
// then combine in fixed order (deterministic).
__global__ __launch_bounds__(256) void k_finred4()
{
    __shared__ float sAv[4][64], sBv[4][64], sAw[4][64], sBw[4][64];
    const int col = blockIdx.x * 64 + (threadIdx.x & 63);
    const int grp = threadIdx.x >> 6;                 // 0..3
    const int s0 = grp * (NSLAB / 4);
    float av = 0.f, bv = 0.f, aw = 0.f, bw = 0.f;
#pragma unroll 4
    for (int s = 0; s < NSLAB / 4; ++s) {
        const size_t o = (size_t)(s0 + s) * DIM + col;
        av += g_pAv[o]; bv += g_pBv[o]; aw += g_pAw[o]; bw += g_pBw[o];
    }
    sAv[grp][threadIdx.x & 63] = av;
    sBv[grp][threadIdx.x & 63] = bv;
    sAw[grp][threadIdx.x & 63] = aw;
    sBw[grp][threadIdx.x & 63] = bw;
    __syncthreads();
    if (grp == 0) {
        const int t = threadIdx.x;                    // 0..63
        g_Av[col] = ((sAv[0][t] + sAv[1][t]) + (sAv[2][t] + sAv[3][t]));
        g_Bv[col] = ((sBv[0][t] + sBv[1][t]) + (sBv[2][t] + sBv[3][t]));
        g_Aw[col] = ((sAw[0][t] + sAw[1][t]) + (sAw[2][t] + sAw[3][t]));
        g_Bw[col] = ((sBw[0][t] + sBw[1][t]) + (sBw[2][t] + sBw[3][t]));
    }
}

// ---------------------------------------------------------------------------
// Scan V[i+1] = Av[i] + Bv[i]*V[i] (V[0]=0) via affine-map composition, then
// W[i+1] = Aw[i] + Bw[i]*V[i], W[0]=0. One block, 1024 threads, 4 elems each.
__global__ __launch_bounds__(1024) void k_scanw()
{
    __shared__ float sa[1024];
    __shared__ float sb[1024];
    const int t = threadIdx.x;
    float la[4], lb[4];
    la[0] = g_Av[4 * t];
    lb[0] = g_Bv[4 * t];
#pragma unroll
    for (int k = 1; k < 4; ++k) {
        const float A = g_Av[4 * t + k];
        const float B = g_Bv[4 * t + k];
        la[k] = fmaf(B, la[k - 1], A);
        lb[k] = B * lb[k - 1];
    }
    sa[t] = la[3];
    sb[t] = lb[3];
    __syncthreads();
#pragma unroll
    for (int off = 1; off < 1024; off <<= 1) {
        float pa = 0.f, pb = 0.f;
        const bool has = (t >= off);
        if (has) { pa = sa[t - off]; pb = sb[t - off]; }
        __syncthreads();
        if (has) {
            sa[t] = fmaf(sb[t], pa, sa[t]);
            sb[t] = sb[t] * pb;
        }
        __syncthreads();
    }
    const float pa = (t > 0) ? sa[t - 1] : 0.f;       // V[4t]
    // V[4t+k] for k=0..3:  pa, then fmaf(lb[k-1], pa, la[k-1])
    float V[4];
    V[0] = pa;
#pragma unroll
    for (int k = 1; k < 4; ++k)
        V[k] = fmaf(lb[k - 1], pa, la[k - 1]);
#pragma unroll
    for (int k = 0; k < 4; ++k) {
        const int i = 4 * t + k;
        g_W[i + 1] = fmaf(g_Bw[i], V[k], g_Aw[i]);
    }
    if (t == 0) g_W[0] = 0.f;
}

// ---------------------------------------------------------------------------
// z[b,i] = leaky(y*x[b,i] + W_i + b0); logdet[b] = DIM*log|y| + cnt_neg*log(alpha)
__global__ __launch_bounds__(256) void k_z(
    const float* __restrict__ x,
    const float* __restrict__ y_p,
    const float* __restrict__ b_p,
    float* __restrict__ out)
{
    const int row = blockIdx.x;
    const float y0 = y_p[0];
    const float bb = b_p[0];
    const float4* __restrict__ xr = (const float4*)(x + (size_t)row * DIM);
    float4* __restrict__ zr = (float4*)(out + (size_t)row * DIM);
    float cnt = 0.f;
#pragma unroll
    for (int j = 0; j < DIM / 4 / 256; ++j) {   // 4 iterations
        const int c = j * 256 + threadIdx.x;
        const float4 xv = xr[c];
        const float4 wv = *(const float4*)&g_W[4 * c];
        float4 z;
        const float l0 = fmaf(y0, xv.x, wv.x + bb);
        const float l1 = fmaf(y0, xv.y, wv.y + bb);
        const float l2 = fmaf(y0, xv.z, wv.z + bb);
        const float l3 = fmaf(y0, xv.w, wv.w + bb);
        z.x = (l0 >= 0.f) ? l0 : ALPHA * l0; if (l0 < 0.f) cnt += 1.f;
        z.y = (l1 >= 0.f) ? l1 : ALPHA * l1; if (l1 < 0.f) cnt += 1.f;
        z.z = (l2 >= 0.f) ? l2 : ALPHA * l2; if (l2 < 0.f) cnt += 1.f;
        z.w = (l3 >= 0.f) ? l3 : ALPHA * l3; if (l3 < 0.f) cnt += 1.f;
        zr[c] = z;
    }
    __shared__ float sm[8];
    const float c = block_reduce_256(cnt, sm);
    if (threadIdx.x == 0)
        out[(size_t)HID * DIM + row] = c * LOG_ALPHA + (float)DIM * logf(fabsf(y0));
}

// ---------------------------------------------------------------------------
extern "C" void kernel_launch(void* const* d_in, const int* in_sizes, int n_in,
                              void* d_out, int out_size)
{
    (void)in_sizes; (void)n_in; (void)out_size;
    const float* x = (const float*)d_in[0];   // [HID, DIM]
    const float* y = (const float*)d_in[1];   // [1]
    const float* w = (const float*)d_in[2];   // [HID]
    const float* b = (const float*)d_in[3];   // [1]
    const float* u = (const float*)d_in[4];   // [1]
    const float* v = (const float*)d_in[5];   // [HID]
    const float* a = (const float*)d_in[6];   // [1]
    float* out = (float*)d_out;               // [HID*DIM] z + [HID] logdet

    k_red4<<<dim3(DIM / ICHUNK, NSLAB), 256>>>(x, v, w, u, a);
    k_finred4<<<DIM / 64, 256>>>();
    k_scanw<<<1, 1024>>>();
    k_z<<<HID, 256>>>(x, y, b, out);
}